// round 4
// baseline (speedup 1.0000x reference)
#include <cuda_runtime.h>
#include <math.h>
#include <stdint.h>

// Problem dims
#define BB 64
#define TT 20
#define CC 512
#define HWW 196
#define VV 10000
#define EE 256
#define UU 512
#define XK 1280   // E + C + U  (gates K)  ==  U + C + E (outs K)
#define G4 2048   // 4*U
#define KSPLIT 4

// ---------------- scratch (static device allocations; no runtime alloc) ----------------
__device__ float g_featsT[BB * HWW * CC];        // [B, HW, C]
__device__ float g_fmean[BB * CC];               // [B, C]
__device__ float g_keys[BB * HWW * UU];          // [B, HW, U]
__device__ float g_xh[BB * XK];                  // per-step input vec: [emb(256) | a(512) | hid(512)]
__device__ float g_cell[BB * UU];
__device__ float g_gates4[KSPLIT * BB * G4];     // split-K partials of gates
__device__ float g_outs[BB * TT * XK];           // [hid(512) | a(512) | emb(256)] per (b,t)
__device__ float g_Wcat[G4 * XK];                // [W_ih | W_hh] columns concat
__device__ float g_biascat[G4];                  // b_ih + b_hh
__device__ float g_attn_scratch[BB * TT * HWW];  // fallback if attn not in d_out

// ---------------- generic NT GEMM: Cm[m,n] = sum_k A[m,k]*W[n,k] (+bias[n]) ----------------
// A: M x (>=K) row-major with row stride lda (K contiguous)
// W: N x (>=K) row-major with row stride ldw (K contiguous)
// gridDim.z = split-K count; each z handles Kslice columns starting at z*Kslice,
// writing to Cm + z*M*ldc (bias only meaningful when gridDim.z==1).
template <int BM, int BN, int BK, int TM, int TN, bool VEC>
__global__ void gemm_nt(const float* __restrict__ A, int lda,
                        const float* __restrict__ W, int ldw,
                        const float* __restrict__ bias,
                        float* __restrict__ Cm, int ldc,
                        int M, int N, int Kslice) {
    constexpr int TX = BN / TN;
    constexpr int TY = BM / TM;
    constexpr int NT = TX * TY;
    constexpr int PAD = 4;
    __shared__ __align__(16) float As[BK * (BM + PAD)];
    __shared__ __align__(16) float Ws[BK * (BN + PAD)];

    const int tid = threadIdx.x;
    const int tx = tid % TX;
    const int ty = tid / TX;
    const int m0 = blockIdx.y * BM;
    const int n0 = blockIdx.x * BN;
    const int kbeg = blockIdx.z * Kslice;
    const int kend = kbeg + Kslice;

    float acc[TM][TN];
#pragma unroll
    for (int i = 0; i < TM; i++)
#pragma unroll
        for (int j = 0; j < TN; j++) acc[i][j] = 0.f;

    for (int k0 = kbeg; k0 < kend; k0 += BK) {
        // stage A tile (BM x BK), stored k-major transposed into As[k][m]
        constexpr int AF4 = BM * BK / 4;
        for (int idx = tid; idx < AF4; idx += NT) {
            int r = idx / (BK / 4);
            int kc = idx % (BK / 4);
            int gm = m0 + r;
            float4 v = make_float4(0.f, 0.f, 0.f, 0.f);
            if (gm < M) v = *reinterpret_cast<const float4*>(&A[(size_t)gm * lda + k0 + kc * 4]);
            As[(kc * 4 + 0) * (BM + PAD) + r] = v.x;
            As[(kc * 4 + 1) * (BM + PAD) + r] = v.y;
            As[(kc * 4 + 2) * (BM + PAD) + r] = v.z;
            As[(kc * 4 + 3) * (BM + PAD) + r] = v.w;
        }
        // stage W tile (BN x BK) into Ws[k][n]
        constexpr int WF4 = BN * BK / 4;
        for (int idx = tid; idx < WF4; idx += NT) {
            int r = idx / (BK / 4);
            int kc = idx % (BK / 4);
            int gn = n0 + r;
            float4 v = make_float4(0.f, 0.f, 0.f, 0.f);
            if (gn < N) v = *reinterpret_cast<const float4*>(&W[(size_t)gn * ldw + k0 + kc * 4]);
            Ws[(kc * 4 + 0) * (BN + PAD) + r] = v.x;
            Ws[(kc * 4 + 1) * (BN + PAD) + r] = v.y;
            Ws[(kc * 4 + 2) * (BN + PAD) + r] = v.z;
            Ws[(kc * 4 + 3) * (BN + PAD) + r] = v.w;
        }
        __syncthreads();

#pragma unroll
        for (int k = 0; k < BK; k++) {
            float a[TM], bv[TN];
            if constexpr (VEC) {
#pragma unroll
                for (int i = 0; i < TM; i += 4)
                    *reinterpret_cast<float4*>(&a[i]) =
                        *reinterpret_cast<const float4*>(&As[k * (BM + PAD) + ty * TM + i]);
#pragma unroll
                for (int j = 0; j < TN; j += 4)
                    *reinterpret_cast<float4*>(&bv[j]) =
                        *reinterpret_cast<const float4*>(&Ws[k * (BN + PAD) + tx * TN + j]);
            } else {
#pragma unroll
                for (int i = 0; i < TM; i++) a[i] = As[k * (BM + PAD) + ty * TM + i];
#pragma unroll
                for (int j = 0; j < TN; j++) bv[j] = Ws[k * (BN + PAD) + tx * TN + j];
            }
#pragma unroll
            for (int i = 0; i < TM; i++)
#pragma unroll
                for (int j = 0; j < TN; j++) acc[i][j] = fmaf(a[i], bv[j], acc[i][j]);
        }
        __syncthreads();
    }

    float* Cz = Cm + (size_t)blockIdx.z * (size_t)M * (size_t)ldc;
#pragma unroll
    for (int i = 0; i < TM; i++) {
        int gm = m0 + ty * TM + i;
        if (gm >= M) continue;
#pragma unroll
        for (int j = 0; j < TN; j++) {
            int gn = n0 + tx * TN + j;
            if (gn < N) {
                float v = acc[i][j];
                if (bias) v += bias[gn];
                Cz[(size_t)gm * ldc + gn] = v;
            }
        }
    }
}

// ---------------- small kernels ----------------

// featsT[b,k,c] = imgf[b,c,k]
__global__ void transpose_kernel(const float* __restrict__ imgf) {
    __shared__ float tile[32][33];
    int b = blockIdx.z;
    int k0 = blockIdx.x * 32, c0 = blockIdx.y * 32;
    int tx = threadIdx.x, ty = threadIdx.y;  // 32 x 8
#pragma unroll
    for (int j = 0; j < 32; j += 8) {
        int c = c0 + ty + j, k = k0 + tx;
        if (c < CC && k < HWW) tile[ty + j][tx] = imgf[((size_t)b * CC + c) * HWW + k];
    }
    __syncthreads();
#pragma unroll
    for (int j = 0; j < 32; j += 8) {
        int k = k0 + ty + j, c = c0 + tx;
        if (k < HWW && c < CC) g_featsT[((size_t)b * HWW + k) * CC + c] = tile[tx][ty + j];
    }
}

__global__ void fmean_kernel(const float* __restrict__ imgf) {
    int i = blockIdx.x * blockDim.x + threadIdx.x;  // over B*C
    if (i >= BB * CC) return;
    const float* row = imgf + (size_t)i * HWW;
    float s = 0.f;
#pragma unroll 4
    for (int k = 0; k < HWW; k++) s += row[k];
    g_fmean[i] = s * (1.0f / HWW);
}

__global__ void wcat_kernel(const float* __restrict__ W_ih, const float* __restrict__ W_hh,
                            const float* __restrict__ b_ih, const float* __restrict__ b_hh) {
    int i = blockIdx.x * blockDim.x + threadIdx.x;
    if (i < G4) g_biascat[i] = b_ih[i] + b_hh[i];
    if (i >= G4 * XK) return;
    int n = i / XK, j = i % XK;
    g_Wcat[i] = (j < CC + EE) ? W_ih[(size_t)n * (CC + EE) + j]
                              : W_hh[(size_t)n * UU + (j - (CC + EE))];
}

// emb gather + max_norm renorm -> outs emb slot for all (b,t)
__global__ void embed_kernel(const float* __restrict__ emb, const int* __restrict__ cap) {
    int r = blockIdx.x;       // B*T
    int tid = threadIdx.x;    // 256 == E
    int ix = cap[r];
    float v = emb[(size_t)ix * EE + tid];
    __shared__ float red[EE];
    red[tid] = v * v;
    __syncthreads();
    for (int s = 128; s > 0; s >>= 1) {
        if (tid < s) red[tid] += red[tid + s];
        __syncthreads();
    }
    float nrm = sqrtf(red[0]);
    float sc = fminf(1.f, 5.f / fmaxf(nrm, 1e-12f));
    g_outs[(size_t)r * XK + (UU + CC) + tid] = v * sc;
}

// attention for one step: scores -> softmax -> context; also stages emb_t into xh
__global__ void attn_step_kernel(const float* __restrict__ imgf, float* __restrict__ attn_out,
                                 int t) {
    int b = blockIdx.x;
    int tid = threadIdx.x;  // 256
    int lane = tid & 31, warp = tid >> 5;
    __shared__ float hid_s[UU];
    __shared__ float sc[HWW];
    __shared__ float red[256];

    hid_s[tid]       = g_xh[b * XK + (EE + CC) + tid];
    hid_s[tid + 256] = g_xh[b * XK + (EE + CC) + tid + 256];
    __syncthreads();

    const float inv_scale = 0.044194173824159216f;  // 1/sqrt(512)
    for (int k = warp; k < HWW; k += 8) {
        const float* kr = g_keys + ((size_t)b * HWW + k) * UU;
        float s = 0.f;
        for (int j = lane; j < UU; j += 32) s = fmaf(hid_s[j], kr[j], s);
#pragma unroll
        for (int o = 16; o > 0; o >>= 1) s += __shfl_down_sync(0xffffffffu, s, o);
        if (lane == 0) sc[k] = s * inv_scale;
    }
    __syncthreads();

    // softmax over 196
    red[tid] = (tid < HWW) ? sc[tid] : -1e30f;
    __syncthreads();
    for (int s = 128; s > 0; s >>= 1) {
        if (tid < s) red[tid] = fmaxf(red[tid], red[tid + s]);
        __syncthreads();
    }
    float mx = red[0];
    __syncthreads();
    float e = (tid < HWW) ? __expf(sc[tid] - mx) : 0.f;
    red[tid] = e;
    __syncthreads();
    for (int s = 128; s > 0; s >>= 1) {
        if (tid < s) red[tid] += red[tid + s];
        __syncthreads();
    }
    float denom = red[0];
    __syncthreads();
    if (tid < HWW) {
        float w = e / denom;
        sc[tid] = w;
        attn_out[((size_t)b * TT + t) * HWW + tid] = w;
    }
    __syncthreads();

    // a[c] = sum_k w[k] * imgf[b,c,k]
    for (int c = warp; c < CC; c += 8) {
        const float* row = imgf + ((size_t)b * CC + c) * HWW;
        float s = 0.f;
        for (int k = lane; k < HWW; k += 32) s = fmaf(sc[k], row[k], s);
#pragma unroll
        for (int o = 16; o > 0; o >>= 1) s += __shfl_down_sync(0xffffffffu, s, o);
        if (lane == 0) {
            g_xh[b * XK + EE + c] = s;
            g_outs[((size_t)b * TT + t) * XK + UU + c] = s;
        }
    }
    // stage emb_t into xh[0:256]
    g_xh[b * XK + tid] = g_outs[((size_t)b * TT + t) * XK + (UU + CC) + tid];
}

__device__ __forceinline__ float sigmoidf_(float x) { return 1.f / (1.f + __expf(-x)); }

// reduce split-K gate partials + bias, LSTM cell update, write hid to xh & outs
__global__ void lstm_kernel(int t) {
    int i = blockIdx.x * blockDim.x + threadIdx.x;
    if (i >= BB * UU) return;
    int b = i >> 9, u = i & 511;
    float gi = 0.f, gf = 0.f, gg = 0.f, go = 0.f;
#pragma unroll
    for (int s = 0; s < KSPLIT; s++) {
        const float* g = g_gates4 + (size_t)s * BB * G4 + (size_t)b * G4;
        gi += g[u];
        gf += g[UU + u];
        gg += g[2 * UU + u];
        go += g[3 * UU + u];
    }
    gi += g_biascat[u];
    gf += g_biascat[UU + u];
    gg += g_biascat[2 * UU + u];
    go += g_biascat[3 * UU + u];
    float cell = g_cell[i];
    float c_new = sigmoidf_(gf) * cell + sigmoidf_(gi) * tanhf(gg);
    float h = sigmoidf_(go) * tanhf(c_new);
    g_cell[i] = c_new;
    g_xh[b * XK + (EE + CC) + u] = h;
    g_outs[((size_t)b * TT + t) * XK + u] = h;
}

// ---------------- launch ----------------
static float* symaddr(const void* sym) {
    void* p = nullptr;
    cudaGetSymbolAddress(&p, sym);
    return (float*)p;
}

extern "C" void kernel_launch(void* const* d_in, const int* in_sizes, int n_in, void* d_out,
                              int out_size) {
    const float* imgf  = (const float*)d_in[0];
    const int*   cap   = (const int*)d_in[1];
    const float* W_h0  = (const float*)d_in[2];
    const float* b_h0  = (const float*)d_in[3];
    const float* W_c0  = (const float*)d_in[4];
    const float* b_c0  = (const float*)d_in[5];
    const float* emb   = (const float*)d_in[6];
    const float* W_key = (const float*)d_in[7];
    const float* b_key = (const float*)d_in[8];
    const float* W_ih  = (const float*)d_in[9];
    const float* b_ih  = (const float*)d_in[10];
    const float* W_hh  = (const float*)d_in[11];
    const float* b_hh  = (const float*)d_in[12];
    const float* W_out = (const float*)d_in[13];
    const float* b_out = (const float*)d_in[14];

    float* logits = (float*)d_out;
    float* attn_out;
    const long long need = (long long)BB * TT * VV + (long long)BB * TT * HWW;
    if ((long long)out_size >= need)
        attn_out = logits + (size_t)BB * TT * VV;
    else
        attn_out = symaddr(g_attn_scratch);

    float* featsT = symaddr(g_featsT);
    float* fmean  = symaddr(g_fmean);
    float* keys   = symaddr(g_keys);
    float* xh     = symaddr(g_xh);
    float* cellp  = symaddr(g_cell);
    float* outs   = symaddr(g_outs);
    float* Wcat   = symaddr(g_Wcat);
    float* gates4 = symaddr(g_gates4);

    // prologue
    transpose_kernel<<<dim3((HWW + 31) / 32, CC / 32, BB), dim3(32, 8)>>>(imgf);
    fmean_kernel<<<(BB * CC + 255) / 256, 256>>>(imgf);
    wcat_kernel<<<(G4 * XK + 255) / 256, 256>>>(W_ih, W_hh, b_ih, b_hh);
    embed_kernel<<<BB * TT, EE>>>(emb, cap);

    // hid0 -> xh[:,768:1280], cell0 -> g_cell
    gemm_nt<64, 32, 16, 4, 2, false><<<dim3(UU / 32, 1, 1), 256>>>(
        fmean, CC, W_h0, CC, b_h0, xh + (EE + CC), XK, BB, UU, CC);
    gemm_nt<64, 32, 16, 4, 2, false><<<dim3(UU / 32, 1, 1), 256>>>(
        fmean, CC, W_c0, CC, b_c0, cellp, UU, BB, UU, CC);

    // keys = featsT @ W_key^T + b_key   (12544 x 512, K=512)
    gemm_nt<128, 64, 16, 8, 4, true><<<dim3(UU / 64, (BB * HWW) / 128, 1), 256>>>(
        featsT, CC, W_key, CC, b_key, keys, UU, BB * HWW, UU, CC);

    // recurrent steps
    for (int t = 0; t < TT; t++) {
        attn_step_kernel<<<BB, 256>>>(imgf, attn_out, t);
        gemm_nt<64, 32, 16, 4, 2, false><<<dim3(G4 / 32, 1, KSPLIT), 256>>>(
            xh, XK, Wcat, XK, nullptr, gates4, G4, BB, G4, XK / KSPLIT);
        lstm_kernel<<<(BB * UU + 255) / 256, 256>>>(t);
    }

    // logits = outs @ W_out^T + b_out   (1280 x 10000, K=1280)
    gemm_nt<128, 64, 16, 8, 4, true><<<dim3((VV + 63) / 64, (BB * TT) / 128, 1), 256>>>(
        outs, XK, W_out, XK, b_out, logits, VV, BB * TT, VV, XK);
}

// round 8
// speedup vs baseline: 1.2993x; 1.2993x over previous
#include <cuda_runtime.h>
#include <cuda_bf16.h>
#include <math.h>
#include <stdint.h>

// Problem dims
#define BB 64
#define TT 20
#define CC 512
#define HWW 196
#define VV 10000
#define EE 256
#define UU 512
#define XK 1280   // E + C + U  (gates K)  ==  U + C + E (outs K)
#define G4 2048   // 4*U
#define KSPLIT 4

// ---------------- scratch (static device allocations; no runtime alloc) ----------------
__device__ float g_featsT[BB * HWW * CC];        // [B, HW, C]
__device__ float g_fmean[BB * CC];               // [B, C]
__device__ float g_keys[BB * HWW * UU];          // [B, HW, U]
__device__ float g_xh[BB * XK];                  // fp32 (only hid slice used by attn)
__device__ float g_cell[BB * UU];
__device__ float g_gates4[KSPLIT * BB * G4];     // split-K partials of gates
__device__ float g_outs[BB * TT * XK];           // [hid(512) | a(512) | emb(256)] per (b,t)
__device__ float g_Wcat[G4 * XK];                // [W_ih | W_hh] columns concat
__device__ float g_biascat[G4];                  // b_ih + b_hh
__device__ float g_attn_scratch[BB * TT * HWW];  // fallback if attn not in d_out

// bf16 hi/lo split operands for tensor-core GEMMs
__device__ __nv_bfloat16 g_Whi[VV * XK];
__device__ __nv_bfloat16 g_Wlo[VV * XK];
__device__ __nv_bfloat16 g_oh[BB * TT * XK];
__device__ __nv_bfloat16 g_ol[BB * TT * XK];
__device__ __nv_bfloat16 g_fh[BB * HWW * CC];
__device__ __nv_bfloat16 g_fl[BB * HWW * CC];
__device__ __nv_bfloat16 g_kh[UU * CC];
__device__ __nv_bfloat16 g_kl[UU * CC];
__device__ __nv_bfloat16 g_xh_h[BB * XK];        // bf16 hi of xh
__device__ __nv_bfloat16 g_xh_l[BB * XK];        // bf16 lo of xh
__device__ __nv_bfloat16 g_wch[G4 * XK];         // bf16 hi of Wcat
__device__ __nv_bfloat16 g_wcl[G4 * XK];         // bf16 lo of Wcat

// ================= portable tensor-core primitives (sm_80+ PTX, OK on sm_103) =================
__device__ __forceinline__ uint32_t smem_to_u32(const void* p) {
    uint32_t a;
    asm("{ .reg .u64 t; cvta.to.shared.u64 t, %1; cvt.u32.u64 %0, t; }" : "=r"(a) : "l"(p));
    return a;
}

#define LDSM_X4(r, addr)                                                            \
    asm volatile("ldmatrix.sync.aligned.m8n8.x4.shared.b16 {%0,%1,%2,%3}, [%4];"    \
                 : "=r"((r)[0]), "=r"((r)[1]), "=r"((r)[2]), "=r"((r)[3])           \
                 : "r"(addr))
#define LDSM_X2(r, addr)                                                            \
    asm volatile("ldmatrix.sync.aligned.m8n8.x2.shared.b16 {%0,%1}, [%2];"          \
                 : "=r"((r)[0]), "=r"((r)[1])                                       \
                 : "r"(addr))
#define MMA_BF16(d, a, b)                                                           \
    asm volatile(                                                                   \
        "mma.sync.aligned.m16n8k16.row.col.f32.bf16.bf16.f32 "                      \
        "{%0,%1,%2,%3}, {%4,%5,%6,%7}, {%8,%9}, {%0,%1,%2,%3};"                     \
        : "+f"((d)[0]), "+f"((d)[1]), "+f"((d)[2]), "+f"((d)[3])                    \
        : "r"((a)[0]), "r"((a)[1]), "r"((a)[2]), "r"((a)[3]),                       \
          "r"((b)[0]), "r"((b)[1]))

__device__ __forceinline__ void cp_async16(uint32_t dst, const void* src, bool pred) {
    int sz = pred ? 16 : 0;
    asm volatile("cp.async.cg.shared.global [%0], [%1], 16, %2;\n"
                 :: "r"(dst), "l"(src), "r"(sz));
}
#define CP_COMMIT() asm volatile("cp.async.commit_group;\n" ::: "memory")
#define CP_WAIT(n)  asm volatile("cp.async.wait_group %0;\n" :: "n"(n) : "memory")

// ---------------- tensor-core split-bf16 NT GEMM ----------------
// C[m,n] = sum_k A[m,k]*B[n,k] (+bias[n])   via AhBh + AhBl + AlBh
// A: M x K rows stride lda (M % BM == 0), B: N x K rows stride ldb, Kslice % 32 == 0.
// gridDim.z = split-K; slice z covers k in [z*Kslice, (z+1)*Kslice), output offset z*M*ldc.
// Block: 256 threads (8 warps, 2 x 4), tile BM x 128, BK=32, 2-stage cp.async pipeline.
template <int BM>
__global__ void __launch_bounds__(256) gemm_mma(
    const __nv_bfloat16* __restrict__ Ah, const __nv_bfloat16* __restrict__ Al, int lda,
    const __nv_bfloat16* __restrict__ Bh, const __nv_bfloat16* __restrict__ Bl, int ldb,
    const float* __restrict__ bias, float* __restrict__ C, int ldc,
    int M, int N, int Kslice) {
    constexpr int ROWB = 80;                    // padded bytes per smem row (64B data + 16B pad)
    constexpr int ATILE = BM * ROWB;
    constexpr int BTILE = 128 * ROWB;
    constexpr int STAGE = 2 * ATILE + 2 * BTILE;
    constexpr int WM = BM / 2;                  // warp tile rows (2 warp-rows)
    constexpr int WN = 32;                      // warp tile cols (4 warp-cols)
    constexpr int FM = WM / 16;
    constexpr int FN = WN / 8;

    extern __shared__ __align__(16) unsigned char sm[];
    const uint32_t sbase = smem_to_u32(sm);

    const int tid = threadIdx.x;
    const int wid = tid >> 5, lane = tid & 31;
    const int warpM = wid & 1, warpN = wid >> 1;
    const int m0 = blockIdx.y * BM;
    const int n0 = blockIdx.x * 128;
    const int kbeg = blockIdx.z * Kslice;
    const int nch = Kslice >> 5;

    float acc[FM][FN][4];
#pragma unroll
    for (int i = 0; i < FM; i++)
#pragma unroll
        for (int j = 0; j < FN; j++)
#pragma unroll
            for (int q = 0; q < 4; q++) acc[i][j][q] = 0.f;

    // ---- async stage loader: chunk ch -> stage s ----
    auto stage_load = [&](int ch, int s) {
        const int k0 = kbeg + (ch << 5);
        const uint32_t stbase = sbase + s * STAGE;
        // A hi/lo tiles: BM rows x 4 16B-chunks
#pragma unroll
        for (int t = 0; t < 2; t++) {
            const __nv_bfloat16* src = t ? Al : Ah;
            const uint32_t dstb = stbase + t * ATILE;
            for (int idx = tid; idx < BM * 4; idx += 256) {
                int row = idx >> 2, c = idx & 3;
                cp_async16(dstb + row * ROWB + c * 16,
                           src + (size_t)(m0 + row) * lda + k0 + c * 8, true);
            }
        }
        // B hi/lo tiles: 128 rows x 4 chunks, predicated on n bounds
#pragma unroll
        for (int t = 0; t < 2; t++) {
            const __nv_bfloat16* src = t ? Bl : Bh;
            const uint32_t dstb = stbase + 2 * ATILE + t * BTILE;
            for (int idx = tid; idx < 128 * 4; idx += 256) {
                int row = idx >> 2, c = idx & 3;
                int gn = n0 + row;
                bool p = gn < N;
                int gr = p ? gn : (N - 1);
                cp_async16(dstb + row * ROWB + c * 16,
                           src + (size_t)gr * ldb + k0 + c * 8, p);
            }
        }
    };

    stage_load(0, 0);
    CP_COMMIT();

    for (int ch = 0; ch < nch; ch++) {
        const int s = ch & 1;
        if (ch + 1 < nch) {
            stage_load(ch + 1, s ^ 1);
            CP_COMMIT();
            CP_WAIT(1);
        } else {
            CP_WAIT(0);
        }
        __syncthreads();

        const uint32_t aHb = sbase + s * STAGE;
        const uint32_t bHb = aHb + 2 * ATILE;
#pragma unroll
        for (int ks = 0; ks < 2; ks++) {
            uint32_t ah[FM][4], al[FM][4];
#pragma unroll
            for (int fm = 0; fm < FM; fm++) {
                uint32_t addr = aHb + (warpM * WM + fm * 16 + (lane & 15)) * ROWB +
                                ((lane >> 4) << 4) + ks * 32;
                LDSM_X4(ah[fm], addr);
                LDSM_X4(al[fm], addr + ATILE);
            }
#pragma unroll
            for (int fn = 0; fn < FN; fn++) {
                uint32_t baddr = bHb + (warpN * WN + fn * 8 + (lane & 7)) * ROWB +
                                 (((lane >> 3) & 1) << 4) + ks * 32;
                uint32_t bh[2], bl[2];
                LDSM_X2(bh, baddr);
                LDSM_X2(bl, baddr + BTILE);
#pragma unroll
                for (int fm = 0; fm < FM; fm++) {
                    MMA_BF16(acc[fm][fn], ah[fm], bh);
                    MMA_BF16(acc[fm][fn], ah[fm], bl);
                    MMA_BF16(acc[fm][fn], al[fm], bh);
                }
            }
        }
        __syncthreads();
    }

    // ---- epilogue ----
    float* Cz = C + (size_t)blockIdx.z * (size_t)M * (size_t)ldc;
#pragma unroll
    for (int fm = 0; fm < FM; fm++) {
        int r0 = m0 + warpM * WM + fm * 16 + (lane >> 2);
#pragma unroll
        for (int fn = 0; fn < FN; fn++) {
            int cb = n0 + warpN * WN + fn * 8 + 2 * (lane & 3);
            if (cb >= N) continue;
            float b0 = bias ? bias[cb] : 0.f;
            float b1 = (cb + 1 < N) ? (bias ? bias[cb + 1] : 0.f) : 0.f;
            Cz[(size_t)r0 * ldc + cb] = acc[fm][fn][0] + b0;
            if (cb + 1 < N) Cz[(size_t)r0 * ldc + cb + 1] = acc[fm][fn][1] + b1;
            Cz[(size_t)(r0 + 8) * ldc + cb] = acc[fm][fn][2] + b0;
            if (cb + 1 < N) Cz[(size_t)(r0 + 8) * ldc + cb + 1] = acc[fm][fn][3] + b1;
        }
    }
}

#define STAGE_BYTES(BM_) (2 * ((BM_) * 80) + 2 * (128 * 80))
#define SMEM_MMA_128 (2 * STAGE_BYTES(128))  // 81920
#define SMEM_MMA_64  (2 * STAGE_BYTES(64))   // 61440

// fp32 -> bf16 hi + bf16 residual lo (vectorized by 4)
__global__ void split_bf16_kernel(const float4* __restrict__ x, __nv_bfloat162* __restrict__ hi,
                                  __nv_bfloat162* __restrict__ lo, int n4) {
    int i = blockIdx.x * blockDim.x + threadIdx.x;
    if (i >= n4) return;
    float4 v = x[i];
    __nv_bfloat16 h0 = __float2bfloat16(v.x), h1 = __float2bfloat16(v.y);
    __nv_bfloat16 h2 = __float2bfloat16(v.z), h3 = __float2bfloat16(v.w);
    float r0 = v.x - __bfloat162float(h0), r1 = v.y - __bfloat162float(h1);
    float r2 = v.z - __bfloat162float(h2), r3 = v.w - __bfloat162float(h3);
    hi[2 * i] = __halves2bfloat162(h0, h1);
    hi[2 * i + 1] = __halves2bfloat162(h2, h3);
    lo[2 * i] = __halves2bfloat162(__float2bfloat16(r0), __float2bfloat16(r1));
    lo[2 * i + 1] = __halves2bfloat162(__float2bfloat16(r2), __float2bfloat16(r3));
}

__device__ __forceinline__ void split1(float v, __nv_bfloat16* hp, __nv_bfloat16* lp) {
    __nv_bfloat16 h = __float2bfloat16(v);
    *hp = h;
    *lp = __float2bfloat16(v - __bfloat162float(h));
}

// split initial hidden state into bf16 hi/lo xh slots
__global__ void split_hid_kernel() {
    int i = blockIdx.x * blockDim.x + threadIdx.x;
    if (i >= BB * UU) return;
    int b = i >> 9, u = i & 511;
    float v = g_xh[b * XK + (EE + CC) + u];
    split1(v, &g_xh_h[b * XK + (EE + CC) + u], &g_xh_l[b * XK + (EE + CC) + u]);
}

// ---------------- generic NT GEMM (SIMT, used for tiny init GEMMs) ----------------
template <int BM, int BN, int BK, int TM, int TN>
__global__ void gemm_nt(const float* __restrict__ A, int lda,
                        const float* __restrict__ W, int ldw,
                        const float* __restrict__ bias,
                        float* __restrict__ Cm, int ldc,
                        int M, int N, int Kslice) {
    constexpr int TX = BN / TN;
    constexpr int TY = BM / TM;
    constexpr int NT = TX * TY;
    constexpr int PAD = 4;
    __shared__ __align__(16) float As[BK * (BM + PAD)];
    __shared__ __align__(16) float Ws[BK * (BN + PAD)];

    const int tid = threadIdx.x;
    const int tx = tid % TX;
    const int ty = tid / TX;
    const int m0 = blockIdx.y * BM;
    const int n0 = blockIdx.x * BN;
    const int kbeg = blockIdx.z * Kslice;
    const int kend = kbeg + Kslice;

    float acc[TM][TN];
#pragma unroll
    for (int i = 0; i < TM; i++)
#pragma unroll
        for (int j = 0; j < TN; j++) acc[i][j] = 0.f;

    for (int k0 = kbeg; k0 < kend; k0 += BK) {
        constexpr int AF4 = BM * BK / 4;
        for (int idx = tid; idx < AF4; idx += NT) {
            int r = idx / (BK / 4);
            int kc = idx % (BK / 4);
            int gm = m0 + r;
            float4 v = make_float4(0.f, 0.f, 0.f, 0.f);
            if (gm < M) v = *reinterpret_cast<const float4*>(&A[(size_t)gm * lda + k0 + kc * 4]);
            As[(kc * 4 + 0) * (BM + PAD) + r] = v.x;
            As[(kc * 4 + 1) * (BM + PAD) + r] = v.y;
            As[(kc * 4 + 2) * (BM + PAD) + r] = v.z;
            As[(kc * 4 + 3) * (BM + PAD) + r] = v.w;
        }
        constexpr int WF4 = BN * BK / 4;
        for (int idx = tid; idx < WF4; idx += NT) {
            int r = idx / (BK / 4);
            int kc = idx % (BK / 4);
            int gn = n0 + r;
            float4 v = make_float4(0.f, 0.f, 0.f, 0.f);
            if (gn < N) v = *reinterpret_cast<const float4*>(&W[(size_t)gn * ldw + k0 + kc * 4]);
            Ws[(kc * 4 + 0) * (BN + PAD) + r] = v.x;
            Ws[(kc * 4 + 1) * (BN + PAD) + r] = v.y;
            Ws[(kc * 4 + 2) * (BN + PAD) + r] = v.z;
            Ws[(kc * 4 + 3) * (BN + PAD) + r] = v.w;
        }
        __syncthreads();

#pragma unroll
        for (int k = 0; k < BK; k++) {
            float a[TM], bv[TN];
#pragma unroll
            for (int i = 0; i < TM; i++) a[i] = As[k * (BM + PAD) + ty * TM + i];
#pragma unroll
            for (int j = 0; j < TN; j++) bv[j] = Ws[k * (BN + PAD) + tx * TN + j];
#pragma unroll
            for (int i = 0; i < TM; i++)
#pragma unroll
                for (int j = 0; j < TN; j++) acc[i][j] = fmaf(a[i], bv[j], acc[i][j]);
        }
        __syncthreads();
    }

    float* Cz = Cm + (size_t)blockIdx.z * (size_t)M * (size_t)ldc;
#pragma unroll
    for (int i = 0; i < TM; i++) {
        int gm = m0 + ty * TM + i;
        if (gm >= M) continue;
#pragma unroll
        for (int j = 0; j < TN; j++) {
            int gn = n0 + tx * TN + j;
            if (gn < N) {
                float v = acc[i][j];
                if (bias) v += bias[gn];
                Cz[(size_t)gm * ldc + gn] = v;
            }
        }
    }
}

// ---------------- small kernels ----------------

__global__ void transpose_kernel(const float* __restrict__ imgf) {
    __shared__ float tile[32][33];
    int b = blockIdx.z;
    int k0 = blockIdx.x * 32, c0 = blockIdx.y * 32;
    int tx = threadIdx.x, ty = threadIdx.y;  // 32 x 8
#pragma unroll
    for (int j = 0; j < 32; j += 8) {
        int c = c0 + ty + j, k = k0 + tx;
        if (c < CC && k < HWW) tile[ty + j][tx] = imgf[((size_t)b * CC + c) * HWW + k];
    }
    __syncthreads();
#pragma unroll
    for (int j = 0; j < 32; j += 8) {
        int k = k0 + ty + j, c = c0 + tx;
        if (k < HWW && c < CC) g_featsT[((size_t)b * HWW + k) * CC + c] = tile[tx][ty + j];
    }
}

__global__ void fmean_kernel(const float* __restrict__ imgf) {
    int i = blockIdx.x * blockDim.x + threadIdx.x;
    if (i >= BB * CC) return;
    const float* row = imgf + (size_t)i * HWW;
    float s = 0.f;
#pragma unroll 4
    for (int k = 0; k < HWW; k++) s += row[k];
    g_fmean[i] = s * (1.0f / HWW);
}

__global__ void wcat_kernel(const float* __restrict__ W_ih, const float* __restrict__ W_hh,
                            const float* __restrict__ b_ih, const float* __restrict__ b_hh) {
    int i = blockIdx.x * blockDim.x + threadIdx.x;
    if (i < G4) g_biascat[i] = b_ih[i] + b_hh[i];
    if (i >= G4 * XK) return;
    int n = i / XK, j = i % XK;
    g_Wcat[i] = (j < CC + EE) ? W_ih[(size_t)n * (CC + EE) + j]
                              : W_hh[(size_t)n * UU + (j - (CC + EE))];
}

__global__ void embed_kernel(const float* __restrict__ emb, const int* __restrict__ cap) {
    int r = blockIdx.x;
    int tid = threadIdx.x;  // 256 == E
    int ix = cap[r];
    float v = emb[(size_t)ix * EE + tid];
    __shared__ float red[EE];
    red[tid] = v * v;
    __syncthreads();
    for (int s = 128; s > 0; s >>= 1) {
        if (tid < s) red[tid] += red[tid + s];
        __syncthreads();
    }
    float nrm = sqrtf(red[0]);
    float sc = fminf(1.f, 5.f / fmaxf(nrm, 1e-12f));
    g_outs[(size_t)r * XK + (UU + CC) + tid] = v * sc;
}

// attention for one step: scores -> softmax -> context; stages emb_t + a into bf16 xh
__global__ void attn_step_kernel(const float* __restrict__ imgf, float* __restrict__ attn_out,
                                 int t) {
    int b = blockIdx.x;
    int tid = threadIdx.x;  // 256
    int lane = tid & 31, warp = tid >> 5;
    __shared__ float hid_s[UU];
    __shared__ float sc[HWW];
    __shared__ float red[256];

    hid_s[tid]       = g_xh[b * XK + (EE + CC) + tid];
    hid_s[tid + 256] = g_xh[b * XK + (EE + CC) + tid + 256];
    __syncthreads();

    const float inv_scale = 0.044194173824159216f;  // 1/sqrt(512)
    for (int k = warp; k < HWW; k += 8) {
        const float* kr = g_keys + ((size_t)b * HWW + k) * UU;
        float s = 0.f;
        for (int j = lane; j < UU; j += 32) s = fmaf(hid_s[j], kr[j], s);
#pragma unroll
        for (int o = 16; o > 0; o >>= 1) s += __shfl_down_sync(0xffffffffu, s, o);
        if (lane == 0) sc[k] = s * inv_scale;
    }
    __syncthreads();

    red[tid] = (tid < HWW) ? sc[tid] : -1e30f;
    __syncthreads();
    for (int s = 128; s > 0; s >>= 1) {
        if (tid < s) red[tid] = fmaxf(red[tid], red[tid + s]);
        __syncthreads();
    }
    float mx = red[0];
    __syncthreads();
    float e = (tid < HWW) ? __expf(sc[tid] - mx) : 0.f;
    red[tid] = e;
    __syncthreads();
    for (int s = 128; s > 0; s >>= 1) {
        if (tid < s) red[tid] += red[tid + s];
        __syncthreads();
    }
    float denom = red[0];
    __syncthreads();
    if (tid < HWW) {
        float w = e / denom;
        sc[tid] = w;
        attn_out[((size_t)b * TT + t) * HWW + tid] = w;
    }
    __syncthreads();

    // a[c] = sum_k w[k] * imgf[b,c,k]
    for (int c = warp; c < CC; c += 8) {
        const float* row = imgf + ((size_t)b * CC + c) * HWW;
        float s = 0.f;
        for (int k = lane; k < HWW; k += 32) s = fmaf(sc[k], row[k], s);
#pragma unroll
        for (int o = 16; o > 0; o >>= 1) s += __shfl_down_sync(0xffffffffu, s, o);
        if (lane == 0) {
            g_outs[((size_t)b * TT + t) * XK + UU + c] = s;
            split1(s, &g_xh_h[b * XK + EE + c], &g_xh_l[b * XK + EE + c]);
        }
    }
    // stage emb_t into bf16 xh[0:256]
    {
        float v = g_outs[((size_t)b * TT + t) * XK + (UU + CC) + tid];
        split1(v, &g_xh_h[b * XK + tid], &g_xh_l[b * XK + tid]);
    }
}

__device__ __forceinline__ float sigmoidf_(float x) { return 1.f / (1.f + __expf(-x)); }

// reduce split-K gate partials + bias, LSTM cell update, write hid (fp32 + bf16 hi/lo)
__global__ void lstm_kernel(int t) {
    int i = blockIdx.x * blockDim.x + threadIdx.x;
    if (i >= BB * UU) return;
    int b = i >> 9, u = i & 511;
    float gi = 0.f, gf = 0.f, gg = 0.f, go = 0.f;
#pragma unroll
    for (int s = 0; s < KSPLIT; s++) {
        const float* g = g_gates4 + (size_t)s * BB * G4 + (size_t)b * G4;
        gi += g[u];
        gf += g[UU + u];
        gg += g[2 * UU + u];
        go += g[3 * UU + u];
    }
    gi += g_biascat[u];
    gf += g_biascat[UU + u];
    gg += g_biascat[2 * UU + u];
    go += g_biascat[3 * UU + u];
    float cell = g_cell[i];
    float c_new = sigmoidf_(gf) * cell + sigmoidf_(gi) * tanhf(gg);
    float h = sigmoidf_(go) * tanhf(c_new);
    g_cell[i] = c_new;
    g_xh[b * XK + (EE + CC) + u] = h;
    split1(h, &g_xh_h[b * XK + (EE + CC) + u], &g_xh_l[b * XK + (EE + CC) + u]);
    g_outs[((size_t)b * TT + t) * XK + u] = h;
}

// ---------------- launch ----------------
static float* symaddr(const void* sym) {
    void* p = nullptr;
    cudaGetSymbolAddress(&p, sym);
    return (float*)p;
}
static __nv_bfloat16* symaddrb(const void* sym) {
    void* p = nullptr;
    cudaGetSymbolAddress(&p, sym);
    return (__nv_bfloat16*)p;
}

extern "C" void kernel_launch(void* const* d_in, const int* in_sizes, int n_in, void* d_out,
                              int out_size) {
    const float* imgf  = (const float*)d_in[0];
    const int*   cap   = (const int*)d_in[1];
    const float* W_h0  = (const float*)d_in[2];
    const float* b_h0  = (const float*)d_in[3];
    const float* W_c0  = (const float*)d_in[4];
    const float* b_c0  = (const float*)d_in[5];
    const float* emb   = (const float*)d_in[6];
    const float* W_key = (const float*)d_in[7];
    const float* b_key = (const float*)d_in[8];
    const float* W_ih  = (const float*)d_in[9];
    const float* b_ih  = (const float*)d_in[10];
    const float* W_hh  = (const float*)d_in[11];
    const float* b_hh  = (const float*)d_in[12];
    const float* W_out = (const float*)d_in[13];
    const float* b_out = (const float*)d_in[14];

    float* logits = (float*)d_out;
    float* attn_out;
    const long long need = (long long)BB * TT * VV + (long long)BB * TT * HWW;
    if ((long long)out_size >= need)
        attn_out = logits + (size_t)BB * TT * VV;
    else
        attn_out = symaddr(g_attn_scratch);

    float* featsT = symaddr(g_featsT);
    float* fmean  = symaddr(g_fmean);
    float* keys   = symaddr(g_keys);
    float* xh     = symaddr(g_xh);
    float* cellp  = symaddr(g_cell);
    float* outs   = symaddr(g_outs);
    float* Wcat   = symaddr(g_Wcat);
    float* gates4 = symaddr(g_gates4);

    __nv_bfloat16* Whi  = symaddrb(g_Whi);
    __nv_bfloat16* Wlo  = symaddrb(g_Wlo);
    __nv_bfloat16* oh   = symaddrb(g_oh);
    __nv_bfloat16* ol   = symaddrb(g_ol);
    __nv_bfloat16* fh   = symaddrb(g_fh);
    __nv_bfloat16* fl   = symaddrb(g_fl);
    __nv_bfloat16* kh   = symaddrb(g_kh);
    __nv_bfloat16* kl   = symaddrb(g_kl);
    __nv_bfloat16* xhh  = symaddrb(g_xh_h);
    __nv_bfloat16* xhl  = symaddrb(g_xh_l);
    __nv_bfloat16* wch  = symaddrb(g_wch);
    __nv_bfloat16* wcl  = symaddrb(g_wcl);

    cudaFuncSetAttribute(gemm_mma<128>, cudaFuncAttributeMaxDynamicSharedMemorySize,
                         SMEM_MMA_128);
    cudaFuncSetAttribute(gemm_mma<64>, cudaFuncAttributeMaxDynamicSharedMemorySize,
                         SMEM_MMA_64);

    // prologue
    transpose_kernel<<<dim3((HWW + 31) / 32, CC / 32, BB), dim3(32, 8)>>>(imgf);
    fmean_kernel<<<(BB * CC + 255) / 256, 256>>>(imgf);
    wcat_kernel<<<(G4 * XK + 255) / 256, 256>>>(W_ih, W_hh, b_ih, b_hh);
    embed_kernel<<<BB * TT, EE>>>(emb, cap);

    // bf16 splits: W_out, W_key, featsT, Wcat
    {
        int n4 = (VV * XK) / 4;
        split_bf16_kernel<<<(n4 + 255) / 256, 256>>>((const float4*)W_out,
                                                     (__nv_bfloat162*)Whi, (__nv_bfloat162*)Wlo, n4);
    }
    {
        int n4 = (UU * CC) / 4;
        split_bf16_kernel<<<(n4 + 255) / 256, 256>>>((const float4*)W_key,
                                                     (__nv_bfloat162*)kh, (__nv_bfloat162*)kl, n4);
    }
    {
        int n4 = (BB * HWW * CC) / 4;
        split_bf16_kernel<<<(n4 + 255) / 256, 256>>>((const float4*)featsT,
                                                     (__nv_bfloat162*)fh, (__nv_bfloat162*)fl, n4);
    }
    {
        int n4 = (G4 * XK) / 4;
        split_bf16_kernel<<<(n4 + 255) / 256, 256>>>((const float4*)Wcat,
                                                     (__nv_bfloat162*)wch, (__nv_bfloat162*)wcl, n4);
    }

    // hid0 -> xh[:,768:1280], cell0 -> g_cell, then split hid0 to bf16
    gemm_nt<64, 32, 16, 4, 2><<<dim3(UU / 32, 1, 1), 256>>>(
        fmean, CC, W_h0, CC, b_h0, xh + (EE + CC), XK, BB, UU, CC);
    gemm_nt<64, 32, 16, 4, 2><<<dim3(UU / 32, 1, 1), 256>>>(
        fmean, CC, W_c0, CC, b_c0, cellp, UU, BB, UU, CC);
    split_hid_kernel<<<(BB * UU + 255) / 256, 256>>>();

    // keys = featsT @ W_key^T + b_key  (12544 x 512, K=512) on tensor cores
    gemm_mma<128><<<dim3(UU / 128, (BB * HWW) / 128, 1), 256, SMEM_MMA_128>>>(
        fh, fl, CC, kh, kl, CC, b_key, keys, UU, BB * HWW, UU, CC);

    // recurrent steps
    for (int t = 0; t < TT; t++) {
        attn_step_kernel<<<BB, 256>>>(imgf, attn_out, t);
        gemm_mma<64><<<dim3(G4 / 128, 1, KSPLIT), 256, SMEM_MMA_64>>>(
            xhh, xhl, XK, wch, wcl, XK, nullptr, gates4, G4, BB, G4, XK / KSPLIT);
        lstm_kernel<<<(BB * UU + 255) / 256, 256>>>(t);
    }

    // split outs, then logits = outs @ W_out^T + b_out on tensor cores
    {
        int n4 = (BB * TT * XK) / 4;
        split_bf16_kernel<<<(n4 + 255) / 256, 256>>>((const float4*)outs,
                                                     (__nv_bfloat162*)oh, (__nv_bfloat162*)ol, n4);
    }
    gemm_mma<128><<<dim3((VV + 127) / 128, (BB * TT) / 128, 1), 256, SMEM_MMA_128>>>(
        oh, ol, XK, Whi, Wlo, XK, b_out, logits, VV, BB * TT, VV, XK);
}